// round 1
// baseline (speedup 1.0000x reference)
#include <cuda_runtime.h>
#include <cuda_bf16.h>

#define H 128
#define NMAX 50048

// ---- scratch (device globals; no allocation allowed) ----
__device__ float g_xw  [NMAX * H];   // x @ W1
__device__ float g_agg1[NMAX * H];   // A_hat (x@W1)
__device__ float g_h   [NMAX * H];   // relu(agg1 + b1)
__device__ float g_agg2[NMAX * H];   // A_hat h
__device__ float g_dinv[NMAX];
__device__ int   g_deg [NMAX];
__device__ float g_Wcp [H * H];      // (W2+W2u) @ Wpca^T
__device__ float g_Wcb [H * H];      // W2u @ Wbce^T
__device__ float g_bcp [H];
__device__ float g_bcb [H];

// ---------------------------------------------------------------------------
// Fold weights: Wcp[m][j] = sum_k (W2+W2u)[m][k]*Wpca[j][k]
//               Wcb[m][j] = sum_k W2u[m][k]*Wbce[j][k]
// grid 128 blocks x 128 threads
// ---------------------------------------------------------------------------
__global__ void k_prep(const float* __restrict__ W2, const float* __restrict__ W2u,
                       const float* __restrict__ Wpca, const float* __restrict__ Wbce,
                       const float* __restrict__ b2, const float* __restrict__ b2u,
                       const float* __restrict__ bpca, const float* __restrict__ bbce) {
    int m = blockIdx.x, j = threadIdx.x;
    float sp = 0.f, sb = 0.f;
    #pragma unroll 8
    for (int k = 0; k < H; k++) {
        float w2s = W2[m * H + k] + W2u[m * H + k];
        sp += w2s * Wpca[j * H + k];
        sb += W2u[m * H + k] * Wbce[j * H + k];
    }
    g_Wcp[m * H + j] = sp;
    g_Wcb[m * H + j] = sb;
    if (m == 0) {
        float bp = bpca[j], bb = bbce[j];
        #pragma unroll 8
        for (int k = 0; k < H; k++) {
            bp += (b2[k] + b2u[k]) * Wpca[j * H + k];
            bb += b2u[k] * Wbce[j * H + k];
        }
        g_bcp[j] = bp;
        g_bcb[j] = bb;
    }
}

// ---------------------------------------------------------------------------
// Degree / normalization
// ---------------------------------------------------------------------------
__global__ void k_deg_init(int n) {
    int i = blockIdx.x * blockDim.x + threadIdx.x;
    if (i < n) g_deg[i] = 1;   // self loop
}

__global__ void k_deg_edge(const int* __restrict__ dst, int E) {
    int e = blockIdx.x * blockDim.x + threadIdx.x;
    if (e < E) atomicAdd(&g_deg[dst[e]], 1);
}

__global__ void k_dinv(int n) {
    int i = blockIdx.x * blockDim.x + threadIdx.x;
    if (i < n) g_dinv[i] = rsqrtf((float)g_deg[i]);
}

// ---------------------------------------------------------------------------
// GEMM: C[n,128] = A[n,128] @ W[128,128] (+ bias). W layout: W[k*128 + j].
// BM=64 rows per block, 256 threads, micro-tile 4x8.
// ---------------------------------------------------------------------------
#define BM 64
#define BK 32

__global__ void k_gemm128(const float* __restrict__ A, const float* __restrict__ W,
                          const float* __restrict__ bias, float* __restrict__ C, int n) {
    __shared__ float As[BM][BK + 4];   // stride 36 floats: 16B aligned, no bank conflicts
    __shared__ float Ws[BK][H];

    int tid = threadIdx.x;               // 0..255
    int tx = tid & 15;                   // col group: cols tx*8..tx*8+7
    int ty = tid >> 4;                   // row group: rows ty*4..ty*4+3
    int row0 = blockIdx.x * BM;

    float acc[4][8];
    #pragma unroll
    for (int i = 0; i < 4; i++)
        #pragma unroll
        for (int j = 0; j < 8; j++) acc[i][j] = 0.f;

    for (int k0 = 0; k0 < H; k0 += BK) {
        // load A tile 64x32 (512 float4, 2 per thread)
        #pragma unroll
        for (int i = 0; i < 2; i++) {
            int idx = tid + i * 256;
            int r = idx >> 3, c4 = (idx & 7) * 4;
            int gr = row0 + r;
            float4 v = make_float4(0.f, 0.f, 0.f, 0.f);
            if (gr < n) v = *(const float4*)(A + (size_t)gr * H + k0 + c4);
            *(float4*)&As[r][c4] = v;
        }
        // load W tile 32x128 (1024 float4, 4 per thread)
        #pragma unroll
        for (int i = 0; i < 4; i++) {
            int idx = tid + i * 256;
            int r = idx >> 5, c4 = (idx & 31) * 4;
            *(float4*)&Ws[r][c4] = *(const float4*)(W + (size_t)(k0 + r) * H + c4);
        }
        __syncthreads();

        #pragma unroll
        for (int kk = 0; kk < BK; kk++) {
            float a0 = As[ty * 4 + 0][kk];
            float a1 = As[ty * 4 + 1][kk];
            float a2 = As[ty * 4 + 2][kk];
            float a3 = As[ty * 4 + 3][kk];
            float4 bl = *(float4*)&Ws[kk][tx * 8];
            float4 bh = *(float4*)&Ws[kk][tx * 8 + 4];
            float b[8] = {bl.x, bl.y, bl.z, bl.w, bh.x, bh.y, bh.z, bh.w};
            #pragma unroll
            for (int j = 0; j < 8; j++) {
                acc[0][j] += a0 * b[j];
                acc[1][j] += a1 * b[j];
                acc[2][j] += a2 * b[j];
                acc[3][j] += a3 * b[j];
            }
        }
        __syncthreads();
    }

    float bv[8];
    #pragma unroll
    for (int j = 0; j < 8; j++) bv[j] = bias ? bias[tx * 8 + j] : 0.f;

    #pragma unroll
    for (int i = 0; i < 4; i++) {
        int gr = row0 + ty * 4 + i;
        if (gr < n) {
            float4 o0 = make_float4(acc[i][0] + bv[0], acc[i][1] + bv[1],
                                    acc[i][2] + bv[2], acc[i][3] + bv[3]);
            float4 o1 = make_float4(acc[i][4] + bv[4], acc[i][5] + bv[5],
                                    acc[i][6] + bv[6], acc[i][7] + bv[7]);
            *(float4*)(C + (size_t)gr * H + tx * 8) = o0;
            *(float4*)(C + (size_t)gr * H + tx * 8 + 4) = o1;
        }
    }
}

// ---------------------------------------------------------------------------
// Self-loop init: agg1[i] = xw[i] * dinv[i]^2   (vectorized float4)
// ---------------------------------------------------------------------------
__global__ void k_selfinit(int n) {
    int idx = blockIdx.x * blockDim.x + threadIdx.x;   // over n*32 float4 groups
    if (idx >= n * 32) return;
    int node = idx >> 5;
    float s = g_dinv[node]; s = s * s;
    float4 v = ((const float4*)g_xw)[idx];
    ((float4*)g_agg1)[idx] = make_float4(v.x * s, v.y * s, v.z * s, v.w * s);
}

// h = relu(agg1 + b1);  agg2 = h * dinv^2  (self-loop init for pass 2)
__global__ void k_relu_selfinit(const float* __restrict__ b1, int n) {
    int idx = blockIdx.x * blockDim.x + threadIdx.x;
    if (idx >= n * 32) return;
    int node = idx >> 5;
    int c4 = (idx & 31) * 4;
    float s = g_dinv[node]; s = s * s;
    float4 v = ((const float4*)g_agg1)[idx];
    float4 b = *(const float4*)(b1 + c4);
    v.x = fmaxf(v.x + b.x, 0.f);
    v.y = fmaxf(v.y + b.y, 0.f);
    v.z = fmaxf(v.z + b.z, 0.f);
    v.w = fmaxf(v.w + b.w, 0.f);
    ((float4*)g_h)[idx] = v;
    ((float4*)g_agg2)[idx] = make_float4(v.x * s, v.y * s, v.z * s, v.w * s);
}

// ---------------------------------------------------------------------------
// Edge aggregation: out[d] += in[s] * dinv[s]*dinv[d].  One warp per edge,
// lane handles 4 floats, vectorized red.global.add.v4.f32 (sm_90+).
// ---------------------------------------------------------------------------
__global__ void k_edge_agg(const int* __restrict__ src, const int* __restrict__ dst,
                           const float* __restrict__ in, float* __restrict__ out, int E) {
    int e = (blockIdx.x * blockDim.x + threadIdx.x) >> 5;
    if (e >= E) return;
    int lane = threadIdx.x & 31;
    int s = __ldg(&src[e]);
    int d = __ldg(&dst[e]);
    float w = g_dinv[s] * g_dinv[d];
    float4 v = *(const float4*)(in + (size_t)s * H + lane * 4);
    float* p = out + (size_t)d * H + lane * 4;
    asm volatile("red.global.add.v4.f32 [%0], {%1,%2,%3,%4};"
                 :: "l"(p), "f"(v.x * w), "f"(v.y * w), "f"(v.z * w), "f"(v.w * w)
                 : "memory");
}

// ---------------------------------------------------------------------------
// out1 = ((feat_label / max(||feat_label||,1e-12)) @ Wh1^T + bh1) / 0.1
// One warp per node.
// ---------------------------------------------------------------------------
__global__ void k_out1(const float* __restrict__ fl, const float* __restrict__ Wh1,
                       const float* __restrict__ bh1, float* __restrict__ out1, int n) {
    int node = (blockIdx.x * blockDim.x + threadIdx.x) >> 5;
    if (node >= n) return;
    int lane = threadIdx.x & 31;
    float4 v = *(const float4*)(fl + (size_t)node * H + lane * 4);
    float ss = v.x * v.x + v.y * v.y + v.z * v.z + v.w * v.w;
    #pragma unroll
    for (int o = 16; o > 0; o >>= 1) ss += __shfl_xor_sync(0xFFFFFFFFu, ss, o);
    float inv = 1.0f / fmaxf(sqrtf(ss), 1e-12f);
    float res[4];
    #pragma unroll
    for (int c = 0; c < 4; c++) {
        float4 w = *(const float4*)(Wh1 + c * H + lane * 4);
        float p = v.x * w.x + v.y * w.y + v.z * w.z + v.w * w.w;
        #pragma unroll
        for (int o = 16; o > 0; o >>= 1) p += __shfl_xor_sync(0xFFFFFFFFu, p, o);
        res[c] = (p * inv + bh1[c]) * 10.0f;   // /0.1
    }
    if (lane == 0)
        *(float4*)(out1 + (size_t)node * 4) = make_float4(res[0], res[1], res[2], res[3]);
}

// ---------------------------------------------------------------------------
extern "C" void kernel_launch(void* const* d_in, const int* in_sizes, int n_in,
                              void* d_out, int out_size) {
    const float* x    = (const float*)d_in[0];
    const int*   ei   = (const int*)d_in[1];
    const float* W1   = (const float*)d_in[2];
    const float* b1   = (const float*)d_in[3];
    const float* W2   = (const float*)d_in[4];
    const float* b2   = (const float*)d_in[5];
    const float* W2u  = (const float*)d_in[6];
    const float* b2u  = (const float*)d_in[7];
    const float* Wh1  = (const float*)d_in[8];
    const float* bh1  = (const float*)d_in[9];
    const float* Wpca = (const float*)d_in[10];
    const float* bpca = (const float*)d_in[11];
    const float* Wbce = (const float*)d_in[12];
    const float* bbce = (const float*)d_in[13];

    int n = in_sizes[0] / H;       // 50000
    int E = in_sizes[1] / 2;       // 800000

    float* out = (float*)d_out;
    float* out1   = out;                            // [n,4]
    float* outpca = out + (size_t)n * 4;            // [n,128]
    float* outbce = outpca + (size_t)n * H;         // [n,128]
    float* outfl  = outbce + (size_t)n * H;         // [n,128]

    const int* src = ei;
    const int* dst = ei + E;

    float *p_xw, *p_agg1, *p_h, *p_agg2, *p_Wcp, *p_Wcb, *p_bcp, *p_bcb;
    cudaGetSymbolAddress((void**)&p_xw,   g_xw);
    cudaGetSymbolAddress((void**)&p_agg1, g_agg1);
    cudaGetSymbolAddress((void**)&p_h,    g_h);
    cudaGetSymbolAddress((void**)&p_agg2, g_agg2);
    cudaGetSymbolAddress((void**)&p_Wcp,  g_Wcp);
    cudaGetSymbolAddress((void**)&p_Wcb,  g_Wcb);
    cudaGetSymbolAddress((void**)&p_bcp,  g_bcp);
    cudaGetSymbolAddress((void**)&p_bcb,  g_bcb);

    const int TB = 256;
    int gN   = (n + TB - 1) / TB;
    int gE   = (E + TB - 1) / TB;
    int gV4  = (n * 32 + TB - 1) / TB;           // n*32 float4 groups
    int gW   = (E * 32 + TB - 1) / TB;           // warp per edge
    int gWn  = (n * 32 + TB - 1) / TB;           // warp per node
    int gG   = (n + BM - 1) / BM;

    // weight folding + degree in parallel with nothing else (serial stream is fine)
    k_prep<<<H, H>>>(W2, W2u, Wpca, Wbce, b2, b2u, bpca, bbce);
    k_deg_init<<<gN, TB>>>(n);
    k_deg_edge<<<gE, TB>>>(dst, E);
    k_dinv<<<gN, TB>>>(n);

    // layer 1
    k_gemm128<<<gG, TB>>>(x, W1, nullptr, p_xw, n);
    k_selfinit<<<gV4, TB>>>(n);
    k_edge_agg<<<gW, TB>>>(src, dst, p_xw, p_agg1, E);
    k_relu_selfinit<<<gV4, TB>>>(b1, n);

    // layer 2 aggregation (single pass, shared by both convs)
    k_edge_agg<<<gW, TB>>>(src, dst, p_h, p_agg2, E);

    // heads
    k_gemm128<<<gG, TB>>>(p_agg2, W2,    b2,    outfl,  n);   // feat_label
    k_gemm128<<<gG, TB>>>(p_agg2, p_Wcp, p_bcp, outpca, n);   // out_pca (folded)
    k_gemm128<<<gG, TB>>>(p_agg2, p_Wcb, p_bcb, outbce, n);   // out_bce (folded)
    k_out1<<<gWn, TB>>>(outfl, Wh1, bh1, out1, n);
}

// round 2
// speedup vs baseline: 1.3006x; 1.3006x over previous
#include <cuda_runtime.h>
#include <cuda_bf16.h>

#define H 128
#define NMAX 50048
#define EMAX (1 << 20)

// ---- scratch (device globals; no allocation allowed) ----
__device__ float g_xw  [NMAX * H];   // x @ W1
__device__ float g_h   [NMAX * H];   // relu(A_hat(x@W1) + b1)
__device__ float g_agg2[NMAX * H];   // A_hat h
__device__ float g_dinv[NMAX];
__device__ int   g_cnt [NMAX];       // edge in-degree (no self loop)
__device__ int   g_rowptr[NMAX];     // CSR row starts (by dst)
__device__ int   g_cursor[NMAX];     // fill cursors
__device__ int   g_part[256];        // scan partials
__device__ int   g_csr [EMAX];       // src indices grouped by dst
__device__ float g_Wcp [H * H];      // (W2+W2u) @ Wpca^T
__device__ float g_Wcb [H * H];      // W2u @ Wbce^T
__device__ float g_bcp [H];
__device__ float g_bcb [H];

// ---- f32x2 packed helpers (sm_100+) -------------------------------------
__device__ __forceinline__ unsigned long long pack2(float a, float b) {
    unsigned long long r;
    asm("mov.b64 %0, {%1,%2};" : "=l"(r) : "f"(a), "f"(b));
    return r;
}
__device__ __forceinline__ void unpack2(unsigned long long v, float& a, float& b) {
    asm("mov.b64 {%0,%1}, %2;" : "=f"(a), "=f"(b) : "l"(v));
}
__device__ __forceinline__ unsigned long long fma2(unsigned long long a,
                                                   unsigned long long b,
                                                   unsigned long long c) {
    unsigned long long d;
    asm("fma.rn.f32x2 %0, %1, %2, %3;" : "=l"(d) : "l"(a), "l"(b), "l"(c));
    return d;
}

// ---------------------------------------------------------------------------
// Fold weights: Wcp = (W2+W2u) @ Wpca^T ; Wcb = W2u @ Wbce^T (plus biases)
// ---------------------------------------------------------------------------
__global__ void k_prep(const float* __restrict__ W2, const float* __restrict__ W2u,
                       const float* __restrict__ Wpca, const float* __restrict__ Wbce,
                       const float* __restrict__ b2, const float* __restrict__ b2u,
                       const float* __restrict__ bpca, const float* __restrict__ bbce) {
    int m = blockIdx.x, j = threadIdx.x;
    float sp = 0.f, sb = 0.f;
    #pragma unroll 8
    for (int k = 0; k < H; k++) {
        float w2s = W2[m * H + k] + W2u[m * H + k];
        sp += w2s * Wpca[j * H + k];
        sb += W2u[m * H + k] * Wbce[j * H + k];
    }
    g_Wcp[m * H + j] = sp;
    g_Wcb[m * H + j] = sb;
    if (m == 0) {
        float bp = bpca[j], bb = bbce[j];
        #pragma unroll 8
        for (int k = 0; k < H; k++) {
            bp += (b2[k] + b2u[k]) * Wpca[j * H + k];
            bb += b2u[k] * Wbce[j * H + k];
        }
        g_bcp[j] = bp;
        g_bcb[j] = bb;
    }
}

// ---------------------------------------------------------------------------
// Degree histogram + CSR build
// ---------------------------------------------------------------------------
__global__ void k_deg_edge(const int* __restrict__ dst, int E) {
    int e = blockIdx.x * blockDim.x + threadIdx.x;
    if (e < E) atomicAdd(&g_cnt[dst[e]], 1);
}

// block-level scan of 256-element chunks of g_cnt; writes block-local
// exclusive prefix to g_rowptr, block totals to g_part
__global__ void k_scan1(int n) {
    __shared__ int sh[256];
    int tid = threadIdx.x;
    int i = blockIdx.x * 256 + tid;
    int v = (i < n) ? g_cnt[i] : 0;
    sh[tid] = v;
    __syncthreads();
    #pragma unroll
    for (int off = 1; off < 256; off <<= 1) {
        int t = (tid >= off) ? sh[tid - off] : 0;
        __syncthreads();
        sh[tid] += t;
        __syncthreads();
    }
    if (i < n) g_rowptr[i] = sh[tid] - v;     // exclusive within block
    if (tid == 255) g_part[blockIdx.x] = sh[255];
}

// single-block exclusive scan of the (<=256) partials
__global__ void k_scan2(int nb) {
    __shared__ int sh[256];
    int tid = threadIdx.x;
    int v = (tid < nb) ? g_part[tid] : 0;
    sh[tid] = v;
    __syncthreads();
    #pragma unroll
    for (int off = 1; off < 256; off <<= 1) {
        int t = (tid >= off) ? sh[tid - off] : 0;
        __syncthreads();
        sh[tid] += t;
        __syncthreads();
    }
    if (tid < nb) g_part[tid] = sh[tid] - v;  // exclusive
}

// finalize: global row_ptr, cursors, dinv
__global__ void k_finalize(int n) {
    int i = blockIdx.x * blockDim.x + threadIdx.x;
    if (i >= n) return;
    int rp = g_rowptr[i] + g_part[i >> 8];
    g_rowptr[i] = rp;
    g_cursor[i] = rp;
    g_dinv[i]   = rsqrtf((float)(g_cnt[i] + 1));
}

__global__ void k_csr_fill(const int* __restrict__ src, const int* __restrict__ dst, int E) {
    int e = blockIdx.x * blockDim.x + threadIdx.x;
    if (e >= E) return;
    int d = dst[e];
    int pos = atomicAdd(&g_cursor[d], 1);
    g_csr[pos] = src[e];
}

// ---------------------------------------------------------------------------
// GEMM: C[n,128] = A[n,128] @ W[128,128] (+bias), f32x2 packed FMA.
// Optionally fuses the out1 head (normalize feat_label row, @Wh1^T, /0.1).
// ---------------------------------------------------------------------------
#define BM 64
#define BK 32

template<bool OUT1>
__global__ void k_gemm128(const float* __restrict__ A, const float* __restrict__ W,
                          const float* __restrict__ bias, float* __restrict__ C,
                          const float* __restrict__ Wh1, const float* __restrict__ bh1,
                          float* __restrict__ out1, int n) {
    __shared__ float As[BM][BK + 4];
    __shared__ float Ws[BK][H];

    int tid = threadIdx.x;               // 0..255
    int tx = tid & 15;                   // col group: cols tx*8..tx*8+7
    int ty = tid >> 4;                   // row group: rows ty*4..ty*4+3
    int row0 = blockIdx.x * BM;

    unsigned long long acc[4][4];        // 4 rows x 4 f32x2 pairs (8 cols)
    #pragma unroll
    for (int i = 0; i < 4; i++)
        #pragma unroll
        for (int j = 0; j < 4; j++) acc[i][j] = 0ull;

    for (int k0 = 0; k0 < H; k0 += BK) {
        #pragma unroll
        for (int i = 0; i < 2; i++) {
            int idx = tid + i * 256;
            int r = idx >> 3, c4 = (idx & 7) * 4;
            int gr = row0 + r;
            float4 v = make_float4(0.f, 0.f, 0.f, 0.f);
            if (gr < n) v = *(const float4*)(A + (size_t)gr * H + k0 + c4);
            *(float4*)&As[r][c4] = v;
        }
        #pragma unroll
        for (int i = 0; i < 4; i++) {
            int idx = tid + i * 256;
            int r = idx >> 5, c4 = (idx & 31) * 4;
            *(float4*)&Ws[r][c4] = *(const float4*)(W + (size_t)(k0 + r) * H + c4);
        }
        __syncthreads();

        #pragma unroll
        for (int kk = 0; kk < BK; kk++) {
            const ulonglong2* wrow = (const ulonglong2*)&Ws[kk][tx * 8];
            ulonglong2 w01 = wrow[0];
            ulonglong2 w23 = wrow[1];
            #pragma unroll
            for (int i = 0; i < 4; i++) {
                float a = As[ty * 4 + i][kk];
                unsigned long long aa = pack2(a, a);
                acc[i][0] = fma2(aa, w01.x, acc[i][0]);
                acc[i][1] = fma2(aa, w01.y, acc[i][1]);
                acc[i][2] = fma2(aa, w23.x, acc[i][2]);
                acc[i][3] = fma2(aa, w23.y, acc[i][3]);
            }
        }
        __syncthreads();
    }

    // unpack + bias
    float accf[4][8];
    float bv[8];
    #pragma unroll
    for (int j = 0; j < 8; j++) bv[j] = bias ? bias[tx * 8 + j] : 0.f;
    #pragma unroll
    for (int i = 0; i < 4; i++)
        #pragma unroll
        for (int j = 0; j < 4; j++) {
            float lo, hi;
            unpack2(acc[i][j], lo, hi);
            accf[i][2 * j]     = lo + bv[2 * j];
            accf[i][2 * j + 1] = hi + bv[2 * j + 1];
        }

    #pragma unroll
    for (int i = 0; i < 4; i++) {
        int gr = row0 + ty * 4 + i;
        if (gr < n) {
            *(float4*)(C + (size_t)gr * H + tx * 8)     = *(float4*)&accf[i][0];
            *(float4*)(C + (size_t)gr * H + tx * 8 + 4) = *(float4*)&accf[i][4];
        }
    }

    if (OUT1) {
        // head weights for this lane's 8 cols (reused across the 4 rows)
        float wreg[4][8];
        float bh[4];
        #pragma unroll
        for (int c = 0; c < 4; c++) {
            bh[c] = bh1[c];
            #pragma unroll
            for (int j = 0; j < 8; j++) wreg[c][j] = Wh1[c * H + tx * 8 + j];
        }
        #pragma unroll
        for (int i = 0; i < 4; i++) {
            float ss = 0.f;
            #pragma unroll
            for (int j = 0; j < 8; j++) ss += accf[i][j] * accf[i][j];
            #pragma unroll
            for (int off = 8; off > 0; off >>= 1)
                ss += __shfl_xor_sync(0xFFFFFFFFu, ss, off, 16);
            float inv = 1.0f / fmaxf(sqrtf(ss), 1e-12f);
            float r[4];
            #pragma unroll
            for (int c = 0; c < 4; c++) {
                float p = 0.f;
                #pragma unroll
                for (int j = 0; j < 8; j++) p += accf[i][j] * wreg[c][j];
                #pragma unroll
                for (int off = 8; off > 0; off >>= 1)
                    p += __shfl_xor_sync(0xFFFFFFFFu, p, off, 16);
                r[c] = (p * inv + bh[c]) * 10.0f;   // /0.1
            }
            int gr = row0 + ty * 4 + i;
            if (tx == 0 && gr < n)
                *(float4*)(out1 + (size_t)gr * 4) = make_float4(r[0], r[1], r[2], r[3]);
        }
    }
}

// ---------------------------------------------------------------------------
// CSR aggregation: one warp per dst node.
// out[d] = dinv[d] * ( sum_{s in N(d)} in[s]*dinv[s]  +  in[d]*dinv[d] )
// RELU variant adds bias and clamps (layer-1 epilogue producing h).
// ---------------------------------------------------------------------------
template<bool RELU>
__global__ void k_agg(const float* __restrict__ in, float* __restrict__ out,
                      const float* __restrict__ bias, int n) {
    int node = (blockIdx.x * blockDim.x + threadIdx.x) >> 5;
    if (node >= n) return;
    int lane = threadIdx.x & 31;
    int start = g_rowptr[node];
    int cnt = g_cnt[node];
    float di = g_dinv[node];

    float4 sv = *(const float4*)(in + (size_t)node * H + lane * 4);
    float4 acc = make_float4(sv.x * di, sv.y * di, sv.z * di, sv.w * di);

    for (int base = 0; base < cnt; base += 32) {
        int idx = base + lane;
        int s = 0; float w = 0.f;
        if (idx < cnt) { s = g_csr[start + idx]; w = g_dinv[s]; }
        int m = min(32, cnt - base);
        for (int j = 0; j < m; j++) {
            int   ss = __shfl_sync(0xFFFFFFFFu, s, j);
            float ww = __shfl_sync(0xFFFFFFFFu, w, j);
            float4 v = *(const float4*)(in + (size_t)ss * H + lane * 4);
            acc.x += v.x * ww;
            acc.y += v.y * ww;
            acc.z += v.z * ww;
            acc.w += v.w * ww;
        }
    }
    acc.x *= di; acc.y *= di; acc.z *= di; acc.w *= di;
    if (RELU) {
        float4 b = *(const float4*)(bias + lane * 4);
        acc.x = fmaxf(acc.x + b.x, 0.f);
        acc.y = fmaxf(acc.y + b.y, 0.f);
        acc.z = fmaxf(acc.z + b.z, 0.f);
        acc.w = fmaxf(acc.w + b.w, 0.f);
    }
    *(float4*)(out + (size_t)node * H + lane * 4) = acc;
}

// ---------------------------------------------------------------------------
extern "C" void kernel_launch(void* const* d_in, const int* in_sizes, int n_in,
                              void* d_out, int out_size) {
    const float* x    = (const float*)d_in[0];
    const int*   ei   = (const int*)d_in[1];
    const float* W1   = (const float*)d_in[2];
    const float* b1   = (const float*)d_in[3];
    const float* W2   = (const float*)d_in[4];
    const float* b2   = (const float*)d_in[5];
    const float* W2u  = (const float*)d_in[6];
    const float* b2u  = (const float*)d_in[7];
    const float* Wh1  = (const float*)d_in[8];
    const float* bh1  = (const float*)d_in[9];
    const float* Wpca = (const float*)d_in[10];
    const float* bpca = (const float*)d_in[11];
    const float* Wbce = (const float*)d_in[12];
    const float* bbce = (const float*)d_in[13];

    int n = in_sizes[0] / H;       // 50000
    int E = in_sizes[1] / 2;       // 800000

    float* out = (float*)d_out;
    float* out1   = out;                            // [n,4]
    float* outpca = out + (size_t)n * 4;            // [n,128]
    float* outbce = outpca + (size_t)n * H;         // [n,128]
    float* outfl  = outbce + (size_t)n * H;         // [n,128]

    const int* src = ei;
    const int* dst = ei + E;

    float *p_xw, *p_h, *p_agg2, *p_Wcp, *p_Wcb, *p_bcp, *p_bcb;
    int *p_cnt;
    cudaGetSymbolAddress((void**)&p_xw,   g_xw);
    cudaGetSymbolAddress((void**)&p_h,    g_h);
    cudaGetSymbolAddress((void**)&p_agg2, g_agg2);
    cudaGetSymbolAddress((void**)&p_Wcp,  g_Wcp);
    cudaGetSymbolAddress((void**)&p_Wcb,  g_Wcb);
    cudaGetSymbolAddress((void**)&p_bcp,  g_bcp);
    cudaGetSymbolAddress((void**)&p_bcb,  g_bcb);
    cudaGetSymbolAddress((void**)&p_cnt,  g_cnt);

    const int TB = 256;
    int gN  = (n + TB - 1) / TB;         // 196
    int gE  = (E + TB - 1) / TB;
    int gW  = (n * 32 + TB - 1) / TB;    // warp per node
    int gG  = (n + BM - 1) / BM;
    int nb  = gN;                        // scan partial count (<=256)

    // CSR build + normalization
    cudaMemsetAsync(p_cnt, 0, (size_t)n * sizeof(int));
    k_deg_edge<<<gE, TB>>>(dst, E);
    k_scan1<<<gN, 256>>>(n);
    k_scan2<<<1, 256>>>(nb);
    k_finalize<<<gN, TB>>>(n);
    k_csr_fill<<<gE, TB>>>(src, dst, E);

    // weight folding
    k_prep<<<H, H>>>(W2, W2u, Wpca, Wbce, b2, b2u, bpca, bbce);

    // layer 1: xw = x@W1, h = relu(A_hat xw + b1)
    k_gemm128<false><<<gG, TB>>>(x, W1, nullptr, p_xw, nullptr, nullptr, nullptr, n);
    k_agg<true><<<gW, TB>>>(p_xw, p_h, b1, n);

    // layer 2 aggregation (shared by all heads)
    k_agg<false><<<gW, TB>>>(p_h, p_agg2, nullptr, n);

    // heads: feat_label (+fused out1), folded pca, folded bce
    k_gemm128<true ><<<gG, TB>>>(p_agg2, W2,    b2,    outfl,  Wh1, bh1, out1, n);
    k_gemm128<false><<<gG, TB>>>(p_agg2, p_Wcp, p_bcp, outpca, nullptr, nullptr, nullptr, n);
    k_gemm128<false><<<gG, TB>>>(p_agg2, p_Wcb, p_bcb, outbce, nullptr, nullptr, nullptr, n);
}

// round 3
// speedup vs baseline: 1.3189x; 1.0140x over previous
#include <cuda_runtime.h>
#include <cuda_bf16.h>

#define H 128
#define NMAX 50048
#define EMAX (1 << 20)

// ---- scratch (device globals; no allocation allowed) ----
__device__ float g_xw  [NMAX * H];   // x @ W1
__device__ float g_h   [NMAX * H];   // relu(A_hat(x@W1) + b1)
__device__ float g_agg2[NMAX * H];   // A_hat h
__device__ float g_dinv[NMAX];
__device__ int   g_cnt [NMAX];       // edge in-degree (no self loop)
__device__ int   g_rowptr[NMAX];     // CSR row starts (by dst)
__device__ int   g_cursor[NMAX];     // fill cursors
__device__ int   g_part[256];        // scan partials
__device__ int   g_csr [EMAX];       // src indices grouped by dst
__device__ float g_wsrc[EMAX];       // dinv[src] per CSR slot
__device__ float g_Wcp [H * H];      // (W2+W2u) @ Wpca^T
__device__ float g_Wcb [H * H];      // W2u @ Wbce^T
__device__ float g_bcp [H];
__device__ float g_bcb [H];

// ---- f32x2 packed helpers (sm_100+) -------------------------------------
__device__ __forceinline__ unsigned long long pack2(float a, float b) {
    unsigned long long r;
    asm("mov.b64 %0, {%1,%2};" : "=l"(r) : "f"(a), "f"(b));
    return r;
}
__device__ __forceinline__ void unpack2(unsigned long long v, float& a, float& b) {
    asm("mov.b64 {%0,%1}, %2;" : "=f"(a), "=f"(b) : "l"(v));
}
__device__ __forceinline__ unsigned long long fma2(unsigned long long a,
                                                   unsigned long long b,
                                                   unsigned long long c) {
    unsigned long long d;
    asm("fma.rn.f32x2 %0, %1, %2, %3;" : "=l"(d) : "l"(a), "l"(b), "l"(c));
    return d;
}

// ---------------------------------------------------------------------------
// Fold weights: Wcp = (W2+W2u) @ Wpca^T ; Wcb = W2u @ Wbce^T (plus biases)
// ---------------------------------------------------------------------------
__global__ void k_prep(const float* __restrict__ W2, const float* __restrict__ W2u,
                       const float* __restrict__ Wpca, const float* __restrict__ Wbce,
                       const float* __restrict__ b2, const float* __restrict__ b2u,
                       const float* __restrict__ bpca, const float* __restrict__ bbce) {
    int m = blockIdx.x, j = threadIdx.x;
    float sp = 0.f, sb = 0.f;
    #pragma unroll 8
    for (int k = 0; k < H; k++) {
        float w2s = W2[m * H + k] + W2u[m * H + k];
        sp += w2s * Wpca[j * H + k];
        sb += W2u[m * H + k] * Wbce[j * H + k];
    }
    g_Wcp[m * H + j] = sp;
    g_Wcb[m * H + j] = sb;
    if (m == 0) {
        float bp = bpca[j], bb = bbce[j];
        #pragma unroll 8
        for (int k = 0; k < H; k++) {
            bp += (b2[k] + b2u[k]) * Wpca[j * H + k];
            bb += b2u[k] * Wbce[j * H + k];
        }
        g_bcp[j] = bp;
        g_bcb[j] = bb;
    }
}

// ---------------------------------------------------------------------------
// Degree histogram + CSR build
// ---------------------------------------------------------------------------
__global__ void k_deg_edge(const int* __restrict__ dst, int E) {
    int e = blockIdx.x * blockDim.x + threadIdx.x;
    if (e < E) atomicAdd(&g_cnt[dst[e]], 1);
}

__global__ void k_scan1(int n) {
    __shared__ int sh[256];
    int tid = threadIdx.x;
    int i = blockIdx.x * 256 + tid;
    int v = (i < n) ? g_cnt[i] : 0;
    sh[tid] = v;
    __syncthreads();
    #pragma unroll
    for (int off = 1; off < 256; off <<= 1) {
        int t = (tid >= off) ? sh[tid - off] : 0;
        __syncthreads();
        sh[tid] += t;
        __syncthreads();
    }
    if (i < n) g_rowptr[i] = sh[tid] - v;     // exclusive within block
    if (tid == 255) g_part[blockIdx.x] = sh[255];
}

__global__ void k_scan2(int nb) {
    __shared__ int sh[256];
    int tid = threadIdx.x;
    int v = (tid < nb) ? g_part[tid] : 0;
    sh[tid] = v;
    __syncthreads();
    #pragma unroll
    for (int off = 1; off < 256; off <<= 1) {
        int t = (tid >= off) ? sh[tid - off] : 0;
        __syncthreads();
        sh[tid] += t;
        __syncthreads();
    }
    if (tid < nb) g_part[tid] = sh[tid] - v;  // exclusive
}

__global__ void k_finalize(int n) {
    int i = blockIdx.x * blockDim.x + threadIdx.x;
    if (i >= n) return;
    int rp = g_rowptr[i] + g_part[i >> 8];
    g_rowptr[i] = rp;
    g_cursor[i] = rp;
    g_dinv[i]   = rsqrtf((float)(g_cnt[i] + 1));
}

__global__ void k_csr_fill(const int* __restrict__ src, const int* __restrict__ dst, int E) {
    int e = blockIdx.x * blockDim.x + threadIdx.x;
    if (e >= E) return;
    int d = dst[e];
    int s = src[e];
    int pos = atomicAdd(&g_cursor[d], 1);
    g_csr [pos] = s;
    g_wsrc[pos] = g_dinv[s];
}

// ---------------------------------------------------------------------------
// Layer-1 GEMM: C[n,128] = A[n,128] @ W[128,128], f32x2 packed FMA.
// ---------------------------------------------------------------------------
#define BM 64
#define BK 32

__global__ void k_gemm128(const float* __restrict__ A, const float* __restrict__ W,
                          float* __restrict__ C, int n) {
    __shared__ float As[BM][BK + 4];
    __shared__ float Ws[BK][H];

    int tid = threadIdx.x;
    int tx = tid & 15;
    int ty = tid >> 4;
    int row0 = blockIdx.x * BM;

    unsigned long long acc[4][4];
    #pragma unroll
    for (int i = 0; i < 4; i++)
        #pragma unroll
        for (int j = 0; j < 4; j++) acc[i][j] = 0ull;

    for (int k0 = 0; k0 < H; k0 += BK) {
        #pragma unroll
        for (int i = 0; i < 2; i++) {
            int idx = tid + i * 256;
            int r = idx >> 3, c4 = (idx & 7) * 4;
            int gr = row0 + r;
            float4 v = make_float4(0.f, 0.f, 0.f, 0.f);
            if (gr < n) v = *(const float4*)(A + (size_t)gr * H + k0 + c4);
            *(float4*)&As[r][c4] = v;
        }
        #pragma unroll
        for (int i = 0; i < 4; i++) {
            int idx = tid + i * 256;
            int r = idx >> 5, c4 = (idx & 31) * 4;
            *(float4*)&Ws[r][c4] = *(const float4*)(W + (size_t)(k0 + r) * H + c4);
        }
        __syncthreads();

        #pragma unroll
        for (int kk = 0; kk < BK; kk++) {
            const ulonglong2* wrow = (const ulonglong2*)&Ws[kk][tx * 8];
            ulonglong2 w01 = wrow[0];
            ulonglong2 w23 = wrow[1];
            #pragma unroll
            for (int i = 0; i < 4; i++) {
                float a = As[ty * 4 + i][kk];
                unsigned long long aa = pack2(a, a);
                acc[i][0] = fma2(aa, w01.x, acc[i][0]);
                acc[i][1] = fma2(aa, w01.y, acc[i][1]);
                acc[i][2] = fma2(aa, w23.x, acc[i][2]);
                acc[i][3] = fma2(aa, w23.y, acc[i][3]);
            }
        }
        __syncthreads();
    }

    #pragma unroll
    for (int i = 0; i < 4; i++) {
        int gr = row0 + ty * 4 + i;
        if (gr < n) {
            float o[8];
            #pragma unroll
            for (int j = 0; j < 4; j++) unpack2(acc[i][j], o[2 * j], o[2 * j + 1]);
            *(float4*)(C + (size_t)gr * H + tx * 8)     = *(float4*)&o[0];
            *(float4*)(C + (size_t)gr * H + tx * 8 + 4) = *(float4*)&o[4];
        }
    }
}

// ---------------------------------------------------------------------------
// Merged 3-head GEMM: reads agg2 once per tile, computes
//   outfl  = A@W2  + b2      (+ fused out1 head)
//   outpca = A@Wcp + bcp
//   outbce = A@Wcb + bcb
// BK=16 to keep static smem under 48KB (As 5.1KB + Ws 24KB).
// ---------------------------------------------------------------------------
#define HBK 16

__global__ void __launch_bounds__(256, 1)
k_heads3(const float* __restrict__ A,
         const float* __restrict__ W2, const float* __restrict__ b2,
         const float* __restrict__ Wh1, const float* __restrict__ bh1,
         float* __restrict__ outfl, float* __restrict__ outpca,
         float* __restrict__ outbce, float* __restrict__ out1, int n) {
    __shared__ float As[BM][HBK + 4];
    __shared__ float Ws[3][HBK][H];

    int tid = threadIdx.x;
    int tx = tid & 15;
    int ty = tid >> 4;
    int row0 = blockIdx.x * BM;

    unsigned long long acc[3][4][4];
    #pragma unroll
    for (int hh = 0; hh < 3; hh++)
        #pragma unroll
        for (int i = 0; i < 4; i++)
            #pragma unroll
            for (int j = 0; j < 4; j++) acc[hh][i][j] = 0ull;

    for (int k0 = 0; k0 < H; k0 += HBK) {
        // As: 64x16 = 256 float4, 1 per thread
        {
            int r = tid >> 2, c4 = (tid & 3) * 4;
            int gr = row0 + r;
            float4 v = make_float4(0.f, 0.f, 0.f, 0.f);
            if (gr < n) v = *(const float4*)(A + (size_t)gr * H + k0 + c4);
            *(float4*)&As[r][c4] = v;
        }
        // Ws: 3 x 16 x 128 = 1536 float4, 6 per thread
        #pragma unroll
        for (int i = 0; i < 2; i++) {
            int idx = tid + i * 256;
            int r = idx >> 5, c4 = (idx & 31) * 4;
            *(float4*)&Ws[0][r][c4] = *(const float4*)(W2 + (size_t)(k0 + r) * H + c4);
            *(float4*)&Ws[1][r][c4] = *(const float4*)(g_Wcp + (size_t)(k0 + r) * H + c4);
            *(float4*)&Ws[2][r][c4] = *(const float4*)(g_Wcb + (size_t)(k0 + r) * H + c4);
        }
        __syncthreads();

        #pragma unroll
        for (int kk = 0; kk < HBK; kk++) {
            unsigned long long aa[4];
            #pragma unroll
            for (int i = 0; i < 4; i++) {
                float a = As[ty * 4 + i][kk];
                aa[i] = pack2(a, a);
            }
            #pragma unroll
            for (int hh = 0; hh < 3; hh++) {
                const ulonglong2* wrow = (const ulonglong2*)&Ws[hh][kk][tx * 8];
                ulonglong2 w01 = wrow[0];
                ulonglong2 w23 = wrow[1];
                #pragma unroll
                for (int i = 0; i < 4; i++) {
                    acc[hh][i][0] = fma2(aa[i], w01.x, acc[hh][i][0]);
                    acc[hh][i][1] = fma2(aa[i], w01.y, acc[hh][i][1]);
                    acc[hh][i][2] = fma2(aa[i], w23.x, acc[hh][i][2]);
                    acc[hh][i][3] = fma2(aa[i], w23.y, acc[hh][i][3]);
                }
            }
        }
        __syncthreads();
    }

    // biases
    float bv0[8], bv1[8], bv2[8];
    #pragma unroll
    for (int j = 0; j < 8; j++) {
        bv0[j] = b2   [tx * 8 + j];
        bv1[j] = g_bcp[tx * 8 + j];
        bv2[j] = g_bcb[tx * 8 + j];
    }

    float fl[4][8];   // head-0 values kept for out1
    #pragma unroll
    for (int i = 0; i < 4; i++) {
        int gr = row0 + ty * 4 + i;
        float o1[8], o2[8];
        #pragma unroll
        for (int j = 0; j < 4; j++) {
            unpack2(acc[0][i][j], fl[i][2 * j], fl[i][2 * j + 1]);
            unpack2(acc[1][i][j], o1[2 * j], o1[2 * j + 1]);
            unpack2(acc[2][i][j], o2[2 * j], o2[2 * j + 1]);
        }
        #pragma unroll
        for (int j = 0; j < 8; j++) {
            fl[i][j] += bv0[j];
            o1[j] += bv1[j];
            o2[j] += bv2[j];
        }
        if (gr < n) {
            *(float4*)(outfl  + (size_t)gr * H + tx * 8)     = *(float4*)&fl[i][0];
            *(float4*)(outfl  + (size_t)gr * H + tx * 8 + 4) = *(float4*)&fl[i][4];
            *(float4*)(outpca + (size_t)gr * H + tx * 8)     = *(float4*)&o1[0];
            *(float4*)(outpca + (size_t)gr * H + tx * 8 + 4) = *(float4*)&o1[4];
            *(float4*)(outbce + (size_t)gr * H + tx * 8)     = *(float4*)&o2[0];
            *(float4*)(outbce + (size_t)gr * H + tx * 8 + 4) = *(float4*)&o2[4];
        }
    }

    // fused out1 head: normalize feat_label rows, @Wh1^T, +bh1, /0.1
    float wreg[4][8];
    float bh[4];
    #pragma unroll
    for (int c = 0; c < 4; c++) {
        bh[c] = bh1[c];
        #pragma unroll
        for (int j = 0; j < 8; j++) wreg[c][j] = Wh1[c * H + tx * 8 + j];
    }
    #pragma unroll
    for (int i = 0; i < 4; i++) {
        float ss = 0.f;
        #pragma unroll
        for (int j = 0; j < 8; j++) ss += fl[i][j] * fl[i][j];
        #pragma unroll
        for (int off = 8; off > 0; off >>= 1)
            ss += __shfl_xor_sync(0xFFFFFFFFu, ss, off, 16);
        float inv = 1.0f / fmaxf(sqrtf(ss), 1e-12f);
        float r[4];
        #pragma unroll
        for (int c = 0; c < 4; c++) {
            float p = 0.f;
            #pragma unroll
            for (int j = 0; j < 8; j++) p += fl[i][j] * wreg[c][j];
            #pragma unroll
            for (int off = 8; off > 0; off >>= 1)
                p += __shfl_xor_sync(0xFFFFFFFFu, p, off, 16);
            r[c] = (p * inv + bh[c]) * 10.0f;
        }
        int gr = row0 + ty * 4 + i;
        if (tx == 0 && gr < n)
            *(float4*)(out1 + (size_t)gr * 4) = make_float4(r[0], r[1], r[2], r[3]);
    }
}

// ---------------------------------------------------------------------------
// CSR aggregation: one warp per dst node, uniform loads (no shfl), unroll 4.
// out[d] = dinv[d] * ( sum_s in[s]*dinv[s] + in[d]*dinv[d] )
// ---------------------------------------------------------------------------
template<bool RELU>
__global__ void k_agg(const float* __restrict__ in, float* __restrict__ out,
                      const float* __restrict__ bias, int n) {
    int node = (blockIdx.x * blockDim.x + threadIdx.x) >> 5;
    if (node >= n) return;
    int lane = threadIdx.x & 31;
    int start = g_rowptr[node];
    int cnt = g_cnt[node];
    float di = g_dinv[node];
    int lo = lane * 4;

    float4 sv = *(const float4*)(in + (size_t)node * H + lo);
    float4 acc = make_float4(sv.x * di, sv.y * di, sv.z * di, sv.w * di);

    int j = 0;
    for (; j + 4 <= cnt; j += 4) {
        int   s0 = __ldg(&g_csr [start + j + 0]);
        int   s1 = __ldg(&g_csr [start + j + 1]);
        int   s2 = __ldg(&g_csr [start + j + 2]);
        int   s3 = __ldg(&g_csr [start + j + 3]);
        float w0 = __ldg(&g_wsrc[start + j + 0]);
        float w1 = __ldg(&g_wsrc[start + j + 1]);
        float w2 = __ldg(&g_wsrc[start + j + 2]);
        float w3 = __ldg(&g_wsrc[start + j + 3]);
        float4 v0 = *(const float4*)(in + (size_t)s0 * H + lo);
        float4 v1 = *(const float4*)(in + (size_t)s1 * H + lo);
        float4 v2 = *(const float4*)(in + (size_t)s2 * H + lo);
        float4 v3 = *(const float4*)(in + (size_t)s3 * H + lo);
        acc.x += v0.x * w0 + v1.x * w1 + v2.x * w2 + v3.x * w3;
        acc.y += v0.y * w0 + v1.y * w1 + v2.y * w2 + v3.y * w3;
        acc.z += v0.z * w0 + v1.z * w1 + v2.z * w2 + v3.z * w3;
        acc.w += v0.w * w0 + v1.w * w1 + v2.w * w2 + v3.w * w3;
    }
    for (; j < cnt; j++) {
        int   s = __ldg(&g_csr [start + j]);
        float w = __ldg(&g_wsrc[start + j]);
        float4 v = *(const float4*)(in + (size_t)s * H + lo);
        acc.x += v.x * w;
        acc.y += v.y * w;
        acc.z += v.z * w;
        acc.w += v.w * w;
    }

    acc.x *= di; acc.y *= di; acc.z *= di; acc.w *= di;
    if (RELU) {
        float4 b = *(const float4*)(bias + lo);
        acc.x = fmaxf(acc.x + b.x, 0.f);
        acc.y = fmaxf(acc.y + b.y, 0.f);
        acc.z = fmaxf(acc.z + b.z, 0.f);
        acc.w = fmaxf(acc.w + b.w, 0.f);
    }
    *(float4*)(out + (size_t)node * H + lo) = acc;
}

// ---------------------------------------------------------------------------
extern "C" void kernel_launch(void* const* d_in, const int* in_sizes, int n_in,
                              void* d_out, int out_size) {
    const float* x    = (const float*)d_in[0];
    const int*   ei   = (const int*)d_in[1];
    const float* W1   = (const float*)d_in[2];
    const float* b1   = (const float*)d_in[3];
    const float* W2   = (const float*)d_in[4];
    const float* b2   = (const float*)d_in[5];
    const float* W2u  = (const float*)d_in[6];
    const float* b2u  = (const float*)d_in[7];
    const float* Wh1  = (const float*)d_in[8];
    const float* bh1  = (const float*)d_in[9];
    const float* Wpca = (const float*)d_in[10];
    const float* bpca = (const float*)d_in[11];
    const float* Wbce = (const float*)d_in[12];
    const float* bbce = (const float*)d_in[13];

    int n = in_sizes[0] / H;       // 50000
    int E = in_sizes[1] / 2;       // 800000

    float* out = (float*)d_out;
    float* out1   = out;                            // [n,4]
    float* outpca = out + (size_t)n * 4;            // [n,128]
    float* outbce = outpca + (size_t)n * H;         // [n,128]
    float* outfl  = outbce + (size_t)n * H;         // [n,128]

    const int* src = ei;
    const int* dst = ei + E;

    float *p_xw, *p_h, *p_agg2;
    int *p_cnt;
    cudaGetSymbolAddress((void**)&p_xw,   g_xw);
    cudaGetSymbolAddress((void**)&p_h,    g_h);
    cudaGetSymbolAddress((void**)&p_agg2, g_agg2);
    cudaGetSymbolAddress((void**)&p_cnt,  g_cnt);

    const int TB = 256;
    int gN  = (n + TB - 1) / TB;         // 196
    int gE  = (E + TB - 1) / TB;
    int gW  = (n * 32 + TB - 1) / TB;    // warp per node
    int gG  = (n + BM - 1) / BM;

    // layer-1 GEMM first (independent of CSR build)
    k_gemm128<<<gG, TB>>>(x, W1, p_xw, n);

    // CSR build + normalization
    cudaMemsetAsync(p_cnt, 0, (size_t)n * sizeof(int));
    k_deg_edge<<<gE, TB>>>(dst, E);
    k_scan1<<<gN, 256>>>(n);
    k_scan2<<<1, 256>>>(gN);
    k_finalize<<<gN, TB>>>(n);
    k_csr_fill<<<gE, TB>>>(src, dst, E);

    // weight folding
    k_prep<<<H, H>>>(W2, W2u, Wpca, Wbce, b2, b2u, bpca, bbce);

    // layer 1 aggregation (+relu+bias), layer 2 aggregation
    k_agg<true ><<<gW, TB>>>(p_xw, p_h, b1, n);
    k_agg<false><<<gW, TB>>>(p_h, p_agg2, nullptr, n);

    // merged heads
    k_heads3<<<gG, TB>>>(p_agg2, W2, b2, Wh1, bh1, outfl, outpca, outbce, out1, n);
}